// round 3
// baseline (speedup 1.0000x reference)
#include <cuda_runtime.h>
#include <math.h>

#define NT 4
#define PT 8192
#define NH 32
#define NU 128

// ---------------- scratch (device globals; no allocations) ----------------
__device__ float g_KT[NT * NU * NU];          // k_w transposed per type
__device__ float g_QK[NT * NU * NU];          // q_w @ k_w^T
__device__ float g_VF[NT * NU * NU];          // v_w @ fc_w
__device__ float g_RAW[(size_t)NT * PT * NH]; // 4 MB: raw attention scores
__device__ float g_M[NT * NH];
__device__ float g_S[NT * NH];

// ---------------- K0a: transpose k_w per type ----------------
__global__ void __launch_bounds__(256) ktrans(const float* __restrict__ kw) {
    __shared__ float tile[32][33];
    int t = blockIdx.z;
    int bx = blockIdx.x * 32, by = blockIdx.y * 32;
    const float* src = kw + (size_t)t * NU * NU;
    float* dst = g_KT + (size_t)t * NU * NU;
    int tx = threadIdx.x, ty = threadIdx.y;
#pragma unroll
    for (int i = 0; i < 32; i += 8)
        tile[ty + i][tx] = src[(by + ty + i) * NU + bx + tx];
    __syncthreads();
#pragma unroll
    for (int i = 0; i < 32; i += 8)
        dst[(bx + ty + i) * NU + by + tx] = tile[tx][ty + i];
}

// ---------------- K0b: QK[t][e][u] = sum_v q_w[t][e][v] * k_w[t][u][v] ----------------
__global__ void __launch_bounds__(128) kqk(const float* __restrict__ qw) {
    int t = blockIdx.y, e = blockIdx.x, u = threadIdx.x;
    const float* q = qw + ((size_t)t * NU + e) * NU;
    const float* kt = g_KT + (size_t)t * NU * NU;
    float acc = 0.f;
#pragma unroll 8
    for (int v = 0; v < NU; ++v)
        acc = fmaf(q[v], kt[v * NU + u], acc);
    g_QK[((size_t)t * NU + e) * NU + u] = acc;
}

// ---------------- K0c: VF[t][w][j] = sum_u v_w[t][w][u] * fc_w[t][u][j] ----------------
__global__ void __launch_bounds__(128) kvf(const float* __restrict__ vw,
                                           const float* __restrict__ fw) {
    int t = blockIdx.y, w = blockIdx.x, j = threadIdx.x;
    const float* vr = vw + ((size_t)t * NU + w) * NU;
    const float* f = fw + (size_t)t * NU * NU;
    float acc = 0.f;
#pragma unroll 8
    for (int u = 0; u < NU; ++u)
        acc = fmaf(vr[u], f[u * NU + j], acc);
    g_VF[((size_t)t * NU + w) * NU + j] = acc;
}

// ============ F1: qk = x@QK (smem-batched GEMV) then raw = hist . qk ============
// 256 thr = 8 warps; 4 entities/warp = 32 entities/block.
// smem: QK 64KB + gathered x 16KB = 80KB -> 2 CTAs/SM.
__global__ void __launch_bounds__(256, 2) f1(const float* __restrict__ state,
                                             const float* __restrict__ hist,
                                             const int* __restrict__ eidx) {
    extern __shared__ float sm[];
    float* sQK = sm;                 // 16384 floats
    float* sX = sm + 16384;          // 32*128 floats
    int t = blockIdx.y;
    int n0 = blockIdx.x * 32;
    int tid = threadIdx.x;
    int lane = tid & 31, warp = tid >> 5;

    float4* sQK4 = (float4*)sQK;
    const float4* w4 = (const float4*)(g_QK + (size_t)t * NU * NU);
#pragma unroll
    for (int i = tid; i < 4096; i += 256) sQK4[i] = w4[i];

    float4* sX4 = (float4*)sX;
#pragma unroll
    for (int i = tid; i < 1024; i += 256) {
        int r = i >> 5, c = i & 31;
        int idx = eidx[t * PT + n0 + r];
        sX4[i] = __ldg((const float4*)(state + (size_t)idx * NU) + c);
    }
    __syncthreads();

    // batched GEMV: one QK float4 load serves 4 entities
    int r0 = warp * 4;
    float4 acc[4];
#pragma unroll
    for (int e = 0; e < 4; ++e) acc[e] = make_float4(0.f, 0.f, 0.f, 0.f);
#pragma unroll 4
    for (int v = 0; v < NU; ++v) {
        float4 b = sQK4[v * 32 + lane];
#pragma unroll
        for (int e = 0; e < 4; ++e) {
            float a = sX[(r0 + e) * NU + v];   // broadcast
            acc[e].x = fmaf(a, b.x, acc[e].x);
            acc[e].y = fmaf(a, b.y, acc[e].y);
            acc[e].z = fmaf(a, b.z, acc[e].z);
            acc[e].w = fmaf(a, b.w, acc[e].w);
        }
    }

    // hist stream: raw[h] = hist[idx][h][:] . qk
#pragma unroll
    for (int e = 0; e < 4; ++e) {
        int n = n0 + r0 + e;
        int idx = eidx[t * PT + n];
        const float4* h4 = (const float4*)(hist + (size_t)idx * NH * NU);
        float4 qk = acc[e];
        float myraw = 0.f;
#pragma unroll 8
        for (int h = 0; h < NH; ++h) {
            float4 r4 = __ldcs(h4 + h * 32 + lane);
            float p = fmaf(r4.x, qk.x, fmaf(r4.y, qk.y, fmaf(r4.z, qk.z, r4.w * qk.w)));
#pragma unroll
            for (int o = 16; o; o >>= 1) p += __shfl_xor_sync(0xffffffffu, p, o);
            if (lane == h) myraw = p;
        }
        g_RAW[((size_t)t * PT + n) * NH + lane] = myraw;
    }
}

// ---------------- K2: per (t,h): max and sum(exp) over 8192 entities ----------------
__global__ void __launch_bounds__(256) k2() {
    int th = blockIdx.x;
    const float* base = g_RAW + ((size_t)(th >> 5)) * PT * NH + (th & 31);
    __shared__ float red[256];
    int tid = threadIdx.x;

    float m = -3.402823466e+38f;
    for (int n = tid; n < PT; n += 256) m = fmaxf(m, base[(size_t)n * NH]);
    red[tid] = m;
    __syncthreads();
#pragma unroll
    for (int s = 128; s; s >>= 1) {
        if (tid < s) red[tid] = fmaxf(red[tid], red[tid + s]);
        __syncthreads();
    }
    float M = red[0];
    __syncthreads();

    float su = 0.f;
    for (int n = tid; n < PT; n += 256) su += expf(base[(size_t)n * NH] - M);
    red[tid] = su;
    __syncthreads();
#pragma unroll
    for (int s = 128; s; s >>= 1) {
        if (tid < s) red[tid] += red[tid + s];
        __syncthreads();
    }
    if (tid == 0) { g_M[th] = M; g_S[th] = red[0]; }
}

// ============ F2: hbar = attn^T hist (stream), out = relu(hbar@VF) + x@qw ============
// smem: buf(VF->qw) 64KB + x 16KB + hbar 16KB + attn 4KB = 100KB -> 2 CTAs/SM.
__global__ void __launch_bounds__(256, 2) f2(const float* __restrict__ state,
                                             const float* __restrict__ hist,
                                             const int* __restrict__ eidx,
                                             const float* __restrict__ qw,
                                             float* __restrict__ out) {
    extern __shared__ float sm[];
    float* sBuf = sm;                // 16384 floats (VF, then qw)
    float* sX = sm + 16384;          // 4096
    float* sHB = sm + 16384 + 4096;  // 4096
    float* sW = sm + 16384 + 8192;   // 1024 (attn weights [32][32])
    int t = blockIdx.y;
    int n0 = blockIdx.x * 32;
    int tid = threadIdx.x;
    int lane = tid & 31, warp = tid >> 5;

    float4* sBuf4 = (float4*)sBuf;
    {
        const float4* w4 = (const float4*)(g_VF + (size_t)t * NU * NU);
#pragma unroll
        for (int i = tid; i < 4096; i += 256) sBuf4[i] = w4[i];
    }
    float4* sX4 = (float4*)sX;
#pragma unroll
    for (int i = tid; i < 1024; i += 256) {
        int r = i >> 5, c = i & 31;
        int idx = eidx[t * PT + n0 + r];
        sX4[i] = __ldg((const float4*)(state + (size_t)idx * NU) + c);
    }
#pragma unroll
    for (int i = tid; i < 1024; i += 256) {
        int r = i >> 5, h = i & 31;
        int n = n0 + r;
        float raw = g_RAW[((size_t)t * PT + n) * NH + h];
        sW[i] = expf(raw - g_M[t * NH + h]) / g_S[t * NH + h];
    }
    __syncthreads();

    // hist stream: hbar[e] = sum_h attn[h] * hist[idx][h][:]
    int r0 = warp * 4;
    float4 hb[4];
#pragma unroll
    for (int e = 0; e < 4; ++e) {
        int n = n0 + r0 + e;
        int idx = eidx[t * PT + n];
        const float4* h4 = (const float4*)(hist + (size_t)idx * NH * NU);
        const float* wrow = sW + (r0 + e) * NH;
        float4 a = make_float4(0.f, 0.f, 0.f, 0.f);
#pragma unroll 8
        for (int h = 0; h < NH; ++h) {
            float4 r4 = __ldcs(h4 + h * 32 + lane);
            float wh = wrow[h];
            a.x = fmaf(wh, r4.x, a.x); a.y = fmaf(wh, r4.y, a.y);
            a.z = fmaf(wh, r4.z, a.z); a.w = fmaf(wh, r4.w, a.w);
        }
        hb[e] = a;
    }
    // park hbar in smem for batched GEMV
#pragma unroll
    for (int e = 0; e < 4; ++e)
        ((float4*)(sHB + (r0 + e) * NU))[lane] = hb[e];
    __syncthreads();

    // GEMV1: a1[e] = hbar[e] @ VF
    float4 a1[4];
#pragma unroll
    for (int e = 0; e < 4; ++e) a1[e] = make_float4(0.f, 0.f, 0.f, 0.f);
#pragma unroll 4
    for (int v = 0; v < NU; ++v) {
        float4 b = sBuf4[v * 32 + lane];
#pragma unroll
        for (int e = 0; e < 4; ++e) {
            float a = sHB[(r0 + e) * NU + v];
            a1[e].x = fmaf(a, b.x, a1[e].x);
            a1[e].y = fmaf(a, b.y, a1[e].y);
            a1[e].z = fmaf(a, b.z, a1[e].z);
            a1[e].w = fmaf(a, b.w, a1[e].w);
        }
    }
    __syncthreads();

    // swap buffer to qw
    {
        const float4* w4 = (const float4*)(qw + (size_t)t * NU * NU);
#pragma unroll
        for (int i = tid; i < 4096; i += 256) sBuf4[i] = w4[i];
    }
    __syncthreads();

    // GEMV2: a2[e] = x[e] @ qw ; combine, store
    float4 a2[4];
#pragma unroll
    for (int e = 0; e < 4; ++e) a2[e] = make_float4(0.f, 0.f, 0.f, 0.f);
#pragma unroll 4
    for (int v = 0; v < NU; ++v) {
        float4 b = sBuf4[v * 32 + lane];
#pragma unroll
        for (int e = 0; e < 4; ++e) {
            float a = sX[(r0 + e) * NU + v];
            a2[e].x = fmaf(a, b.x, a2[e].x);
            a2[e].y = fmaf(a, b.y, a2[e].y);
            a2[e].z = fmaf(a, b.z, a2[e].z);
            a2[e].w = fmaf(a, b.w, a2[e].w);
        }
    }
#pragma unroll
    for (int e = 0; e < 4; ++e) {
        int n = n0 + r0 + e;
        float4 r;
        r.x = fmaxf(a1[e].x, 0.f) + a2[e].x;
        r.y = fmaxf(a1[e].y, 0.f) + a2[e].y;
        r.z = fmaxf(a1[e].z, 0.f) + a2[e].z;
        r.w = fmaxf(a1[e].w, 0.f) + a2[e].w;
        ((float4*)(out + ((size_t)t * PT + n) * NU))[lane] = r;
    }
}

// ---------------- launch ----------------
extern "C" void kernel_launch(void* const* d_in, const int* in_sizes, int n_in,
                              void* d_out, int out_size) {
    const float* state = (const float*)d_in[0];
    const float* hist  = (const float*)d_in[1];
    const int*   eidx  = (const int*)d_in[2];
    const float* qw    = (const float*)d_in[3];
    const float* kw    = (const float*)d_in[4];
    const float* vw    = (const float*)d_in[5];
    const float* fw    = (const float*)d_in[6];
    float* out = (float*)d_out;

    const int F1_SMEM = (16384 + 4096) * 4;               // 80 KB
    const int F2_SMEM = (16384 + 4096 + 4096 + 1024) * 4; // 100 KB
    static bool attr_done = false;
    if (!attr_done) {
        cudaFuncSetAttribute(f1, cudaFuncAttributeMaxDynamicSharedMemorySize, F1_SMEM);
        cudaFuncSetAttribute(f2, cudaFuncAttributeMaxDynamicSharedMemorySize, F2_SMEM);
        attr_done = true;
    }

    ktrans<<<dim3(4, 4, NT), dim3(32, 8)>>>(kw);
    kqk<<<dim3(NU, NT), NU>>>(qw);
    kvf<<<dim3(NU, NT), NU>>>(vw, fw);
    f1<<<dim3(PT / 32, NT), 256, F1_SMEM>>>(state, hist, eidx);
    k2<<<NT * NH, 256>>>();
    f2<<<dim3(PT / 32, NT), 256, F2_SMEM>>>(state, hist, eidx, qw, out);
}